// round 1
// baseline (speedup 1.0000x reference)
#include <cuda_runtime.h>
#include <cstdint>

// GraphNetBlock fused kernel — tf32 mma.sync implementation.
// H=128. Edge MLP fused per 128-edge tile, node MLP fused per 128-node tile.

#define HDIM 128
#define TE 128        // rows (edges/nodes) per block tile
#define KC 32         // k-chunk staged in smem per iteration
#define THREADS 256   // 8 warps

// shared memory layout (float offsets)
#define SW_OFF 0                       // weight chunk: 32 x 136
#define SA_OFF 4352                    // A chunk:      128 x 36
#define HA_OFF (4352 + 4608)           // hidden A:     128 x 132
#define HB_OFF (HA_OFF + 16896)        // hidden B:     128 x 132
#define SMEM_FLOATS (HB_OFF + 16896)   // 42752 floats
#define SMEM_BYTES (SMEM_FLOATS * 4)   // 171008 bytes

// scratch: scatter-add accumulator [N, H], N = 50000
__device__ float g_acc[50000 * HDIM];

__device__ __forceinline__ float to_tf32(float x) {
    unsigned u;
    asm("cvt.rna.tf32.f32 %0, %1;" : "=r"(u) : "f"(x));
    return __uint_as_float(u);
}

__device__ __forceinline__ void mma8(float c[4], const unsigned a[4], const unsigned b[2]) {
    asm volatile(
        "mma.sync.aligned.m16n8k8.row.col.f32.tf32.tf32.f32 "
        "{%0,%1,%2,%3}, {%4,%5,%6,%7}, {%8,%9}, {%0,%1,%2,%3};"
        : "+f"(c[0]), "+f"(c[1]), "+f"(c[2]), "+f"(c[3])
        : "r"(a[0]), "r"(a[1]), "r"(a[2]), "r"(a[3]), "r"(b[0]), "r"(b[1]));
}

// One staged k-chunk of KC: A from smem (stride ASTRIDE), W from smem (stride 136).
// Each warp owns rows [rbase, rbase+16), full 128 output cols (16 n-tiles of 8).
template <int ASTRIDE>
__device__ __forceinline__ void mma_chunk(float c[16][4], const float* As, const float* Ws,
                                          int g, int tig, int rbase) {
#pragma unroll
    for (int k8 = 0; k8 < KC; k8 += 8) {
        unsigned a[4];
        const float* ap = As + (rbase + g) * ASTRIDE + k8 + tig;
        a[0] = __float_as_uint(ap[0]);
        a[1] = __float_as_uint(ap[8 * ASTRIDE]);
        a[2] = __float_as_uint(ap[4]);
        a[3] = __float_as_uint(ap[8 * ASTRIDE + 4]);
        const float* bp = Ws + (k8 + tig) * 136 + g;
#pragma unroll
        for (int j = 0; j < 16; j++) {
            unsigned b[2];
            b[0] = __float_as_uint(bp[8 * j]);
            b[1] = __float_as_uint(bp[4 * 136 + 8 * j]);
            mma8(c[j], a, b);
        }
    }
}

__device__ __forceinline__ void stage_weights(float* sW, const float* W, int kt, int tid) {
    for (int idx = tid; idx < KC * HDIM; idx += THREADS) {
        int kk = idx >> 7, n = idx & 127;
        sW[kk * 136 + n] = to_tf32(W[(size_t)(kt + kk) * HDIM + n]);
    }
}

__device__ __forceinline__ void zero_c(float c[16][4]) {
#pragma unroll
    for (int j = 0; j < 16; j++)
#pragma unroll
        for (int i = 0; i < 4; i++) c[j][i] = 0.f;
}

// bias + relu, store tf32-rounded into hidden smem buffer (stride 132)
__device__ __forceinline__ void bias_relu_store(float c[16][4], const float* bias, float* hdst,
                                                int g, int tig, int rbase) {
#pragma unroll
    for (int j = 0; j < 16; j++) {
        int n0 = 8 * j + 2 * tig;
        float b0 = bias[n0], b1 = bias[n0 + 1];
        hdst[(rbase + g) * 132 + n0]         = to_tf32(fmaxf(c[j][0] + b0, 0.f));
        hdst[(rbase + g) * 132 + n0 + 1]     = to_tf32(fmaxf(c[j][1] + b1, 0.f));
        hdst[(rbase + g + 8) * 132 + n0]     = to_tf32(fmaxf(c[j][2] + b0, 0.f));
        hdst[(rbase + g + 8) * 132 + n0 + 1] = to_tf32(fmaxf(c[j][3] + b1, 0.f));
    }
}

// add final bias, compute LayerNorm stats per row (rows rbase+g and rbase+g+8)
__device__ __forceinline__ void ln_stats(float c[16][4], const float* bias,
                                         int tig, float& mu0, float& rs0, float& mu1, float& rs1) {
    float s0 = 0.f, q0 = 0.f, s1 = 0.f, q1 = 0.f;
#pragma unroll
    for (int j = 0; j < 16; j++) {
        int n0 = 8 * j + 2 * tig;
        float b0 = bias[n0], b1 = bias[n0 + 1];
        c[j][0] += b0; c[j][1] += b1; c[j][2] += b0; c[j][3] += b1;
        s0 += c[j][0] + c[j][1];
        q0 += c[j][0] * c[j][0] + c[j][1] * c[j][1];
        s1 += c[j][2] + c[j][3];
        q1 += c[j][2] * c[j][2] + c[j][3] * c[j][3];
    }
#pragma unroll
    for (int m = 1; m < 4; m <<= 1) {
        s0 += __shfl_xor_sync(0xffffffffu, s0, m);
        q0 += __shfl_xor_sync(0xffffffffu, q0, m);
        s1 += __shfl_xor_sync(0xffffffffu, s1, m);
        q1 += __shfl_xor_sync(0xffffffffu, q1, m);
    }
    mu0 = s0 * (1.f / HDIM);
    mu1 = s1 * (1.f / HDIM);
    float v0 = q0 * (1.f / HDIM) - mu0 * mu0;
    float v1 = q1 * (1.f / HDIM) - mu1 * mu1;
    rs0 = rsqrtf(v0 + 1e-5f);
    rs1 = rsqrtf(v1 + 1e-5f);
}

// ============================ EDGE KERNEL ============================
__global__ void __launch_bounds__(THREADS, 1)
edge_kernel(const int* __restrict__ senders, const int* __restrict__ receivers,
            const float* __restrict__ nodef, const float* __restrict__ edgef,
            const float* __restrict__ eW0, const float* __restrict__ eb0,
            const float* __restrict__ eW1, const float* __restrict__ eb1,
            const float* __restrict__ eW2, const float* __restrict__ eb2,
            const float* __restrict__ egm, const float* __restrict__ ebeta,
            float* __restrict__ out_edge, float* __restrict__ acc, int E) {
    extern __shared__ float sm[];
    float* sW = sm + SW_OFF;
    float* sA = sm + SA_OFF;
    float* hA = sm + HA_OFF;
    float* hB = sm + HB_OFF;

    int tid = threadIdx.x, warp = tid >> 5, lane = tid & 31;
    int g = lane >> 2, tig = lane & 3, rbase = warp * 16;
    int e0 = blockIdx.x * TE;
    int nvalid = min(TE, E - e0);

    float c[16][4];
    zero_c(c);

    // ---- stage 0: K = 384 (gathered concat [sf | rf | ef]) ----
    for (int kt = 0; kt < 3 * HDIM; kt += KC) {
        for (int idx = tid; idx < TE * KC; idx += THREADS) {
            int r = idx >> 5, kk = idx & 31;
            int e = min(e0 + r, E - 1);
            int kg = kt + kk;
            float v;
            if (kg < HDIM)           v = nodef[(size_t)senders[e] * HDIM + kg];
            else if (kg < 2 * HDIM)  v = nodef[(size_t)receivers[e] * HDIM + (kg - HDIM)];
            else                     v = edgef[(size_t)e * HDIM + (kg - 2 * HDIM)];
            sA[r * 36 + kk] = to_tf32(v);
        }
        stage_weights(sW, eW0, kt, tid);
        __syncthreads();
        mma_chunk<36>(c, sA, sW, g, tig, rbase);
        __syncthreads();
    }
    bias_relu_store(c, eb0, hA, g, tig, rbase);
    __syncthreads();

    // ---- stage 1: K = 128 ----
    zero_c(c);
    for (int kt = 0; kt < HDIM; kt += KC) {
        stage_weights(sW, eW1, kt, tid);
        __syncthreads();
        mma_chunk<132>(c, hA + kt, sW, g, tig, rbase);
        __syncthreads();
    }
    bias_relu_store(c, eb1, hB, g, tig, rbase);
    __syncthreads();

    // ---- stage 2: K = 128, no relu ----
    zero_c(c);
    for (int kt = 0; kt < HDIM; kt += KC) {
        stage_weights(sW, eW2, kt, tid);
        __syncthreads();
        mma_chunk<132>(c, hB + kt, sW, g, tig, rbase);
        __syncthreads();
    }

    // ---- LayerNorm + residual + scatter-add ----
    float mu0, rs0, mu1, rs1;
    ln_stats(c, eb2, tig, mu0, rs0, mu1, rs1);

    int r0 = rbase + g, r1 = rbase + g + 8;
    bool ok0 = r0 < nvalid, ok1 = r1 < nvalid;
    size_t e_0 = (size_t)(e0 + r0), e_1 = (size_t)(e0 + r1);
    int rc0 = ok0 ? receivers[e_0] : 0;
    int rc1 = ok1 ? receivers[e_1] : 0;

#pragma unroll
    for (int j = 0; j < 16; j++) {
        int n0 = 8 * j + 2 * tig;
        float g0 = egm[n0], g1 = egm[n0 + 1];
        float be0 = ebeta[n0], be1 = ebeta[n0 + 1];
        if (ok0) {
            float y0 = (c[j][0] - mu0) * rs0 * g0 + be0;
            float y1 = (c[j][1] - mu0) * rs0 * g1 + be1;
            out_edge[e_0 * HDIM + n0]     = y0 + edgef[e_0 * HDIM + n0];
            out_edge[e_0 * HDIM + n0 + 1] = y1 + edgef[e_0 * HDIM + n0 + 1];
            atomicAdd(&acc[(size_t)rc0 * HDIM + n0], y0);
            atomicAdd(&acc[(size_t)rc0 * HDIM + n0 + 1], y1);
        }
        if (ok1) {
            float y0 = (c[j][2] - mu1) * rs1 * g0 + be0;
            float y1 = (c[j][3] - mu1) * rs1 * g1 + be1;
            out_edge[e_1 * HDIM + n0]     = y0 + edgef[e_1 * HDIM + n0];
            out_edge[e_1 * HDIM + n0 + 1] = y1 + edgef[e_1 * HDIM + n0 + 1];
            atomicAdd(&acc[(size_t)rc1 * HDIM + n0], y0);
            atomicAdd(&acc[(size_t)rc1 * HDIM + n0 + 1], y1);
        }
    }
}

// ============================ NODE KERNEL ============================
__global__ void __launch_bounds__(THREADS, 1)
node_kernel(const float* __restrict__ nodef, const float* __restrict__ acc,
            const float* __restrict__ nW0, const float* __restrict__ nb0,
            const float* __restrict__ nW1, const float* __restrict__ nb1,
            const float* __restrict__ nW2, const float* __restrict__ nb2,
            const float* __restrict__ ngm, const float* __restrict__ nbeta,
            float* __restrict__ out_node, int N) {
    extern __shared__ float sm[];
    float* sW = sm + SW_OFF;
    float* sA = sm + SA_OFF;
    float* hA = sm + HA_OFF;
    float* hB = sm + HB_OFF;

    int tid = threadIdx.x, warp = tid >> 5, lane = tid & 31;
    int g = lane >> 2, tig = lane & 3, rbase = warp * 16;
    int n0base = blockIdx.x * TE;
    int nvalid = min(TE, N - n0base);

    float c[16][4];
    zero_c(c);

    // ---- stage 0: K = 256 (concat [nf | acc]) ----
    for (int kt = 0; kt < 2 * HDIM; kt += KC) {
        for (int idx = tid; idx < TE * KC; idx += THREADS) {
            int r = idx >> 5, kk = idx & 31;
            int nd = min(n0base + r, N - 1);
            int kg = kt + kk;
            float v;
            if (kg < HDIM) v = nodef[(size_t)nd * HDIM + kg];
            else           v = acc[(size_t)nd * HDIM + (kg - HDIM)];
            sA[r * 36 + kk] = to_tf32(v);
        }
        stage_weights(sW, nW0, kt, tid);
        __syncthreads();
        mma_chunk<36>(c, sA, sW, g, tig, rbase);
        __syncthreads();
    }
    bias_relu_store(c, nb0, hA, g, tig, rbase);
    __syncthreads();

    // ---- stage 1 ----
    zero_c(c);
    for (int kt = 0; kt < HDIM; kt += KC) {
        stage_weights(sW, nW1, kt, tid);
        __syncthreads();
        mma_chunk<132>(c, hA + kt, sW, g, tig, rbase);
        __syncthreads();
    }
    bias_relu_store(c, nb1, hB, g, tig, rbase);
    __syncthreads();

    // ---- stage 2 ----
    zero_c(c);
    for (int kt = 0; kt < HDIM; kt += KC) {
        stage_weights(sW, nW2, kt, tid);
        __syncthreads();
        mma_chunk<132>(c, hB + kt, sW, g, tig, rbase);
        __syncthreads();
    }

    // ---- LayerNorm + residual ----
    float mu0, rs0, mu1, rs1;
    ln_stats(c, nb2, tig, mu0, rs0, mu1, rs1);

    int r0 = rbase + g, r1 = rbase + g + 8;
    bool ok0 = r0 < nvalid, ok1 = r1 < nvalid;
    size_t nd0 = (size_t)(n0base + r0), nd1 = (size_t)(n0base + r1);

#pragma unroll
    for (int j = 0; j < 16; j++) {
        int n0 = 8 * j + 2 * tig;
        float g0 = ngm[n0], g1 = ngm[n0 + 1];
        float be0 = nbeta[n0], be1 = nbeta[n0 + 1];
        if (ok0) {
            float y0 = (c[j][0] - mu0) * rs0 * g0 + be0;
            float y1 = (c[j][1] - mu0) * rs0 * g1 + be1;
            out_node[nd0 * HDIM + n0]     = y0 + nodef[nd0 * HDIM + n0];
            out_node[nd0 * HDIM + n0 + 1] = y1 + nodef[nd0 * HDIM + n0 + 1];
        }
        if (ok1) {
            float y0 = (c[j][2] - mu1) * rs1 * g0 + be0;
            float y1 = (c[j][3] - mu1) * rs1 * g1 + be1;
            out_node[nd1 * HDIM + n0]     = y0 + nodef[nd1 * HDIM + n0];
            out_node[nd1 * HDIM + n0 + 1] = y1 + nodef[nd1 * HDIM + n0 + 1];
        }
    }
}

__global__ void zero_acc_kernel(float* acc, int n) {
    int i = blockIdx.x * blockDim.x + threadIdx.x;
    if (i < n) acc[i] = 0.f;
}

// ============================ LAUNCH ============================
extern "C" void kernel_launch(void* const* d_in, const int* in_sizes, int n_in,
                              void* d_out, int out_size) {
    const int*   senders   = (const int*)d_in[0];
    const int*   receivers = (const int*)d_in[1];
    const float* nodef     = (const float*)d_in[2];
    const float* edgef     = (const float*)d_in[3];
    const float* eW0 = (const float*)d_in[4];
    const float* eb0 = (const float*)d_in[5];
    const float* eW1 = (const float*)d_in[6];
    const float* eb1 = (const float*)d_in[7];
    const float* eW2 = (const float*)d_in[8];
    const float* eb2 = (const float*)d_in[9];
    const float* eg  = (const float*)d_in[10];
    const float* ebeta = (const float*)d_in[11];
    const float* nW0 = (const float*)d_in[12];
    const float* nb0 = (const float*)d_in[13];
    const float* nW1 = (const float*)d_in[14];
    const float* nb1 = (const float*)d_in[15];
    const float* nW2 = (const float*)d_in[16];
    const float* nb2 = (const float*)d_in[17];
    const float* ng  = (const float*)d_in[18];
    const float* nbeta = (const float*)d_in[19];

    int E = in_sizes[1];            // receivers element count = B*E (B=1)
    int N = in_sizes[2] / HDIM;     // node_features = B*N*H

    float* out_node = (float*)d_out;
    float* out_edge = out_node + (size_t)N * HDIM;

    float* acc = nullptr;
    cudaGetSymbolAddress((void**)&acc, g_acc);

    cudaFuncSetAttribute(edge_kernel, cudaFuncAttributeMaxDynamicSharedMemorySize, SMEM_BYTES);
    cudaFuncSetAttribute(node_kernel, cudaFuncAttributeMaxDynamicSharedMemorySize, SMEM_BYTES);

    int accn = N * HDIM;
    zero_acc_kernel<<<(accn + 255) / 256, 256>>>(acc, accn);
    edge_kernel<<<(E + TE - 1) / TE, THREADS, SMEM_BYTES>>>(
        senders, receivers, nodef, edgef,
        eW0, eb0, eW1, eb1, eW2, eb2, eg, ebeta,
        out_edge, acc, E);
    node_kernel<<<(N + TE - 1) / TE, THREADS, SMEM_BYTES>>>(
        nodef, acc, nW0, nb0, nW1, nb1, nW2, nb2, ng, nbeta,
        out_node, N);
}

// round 2
// speedup vs baseline: 3.9938x; 3.9938x over previous
#include <cuda_runtime.h>
#include <cstdint>

// GraphNetBlock fused kernels — tf32 mma.sync, v2:
//  * 2 CTAs/SM (smem 102KB), warp-private in-place hidden buffer
//  * fragment-layout weight smem (LDS.128, conflict-free)
//  * software-pipelined A/W staging, 1 sync per 32-k chunk
//  * vector red.v2 scatter atomics, streaming stores

#define HDIM 128
#define TE 128
#define KC 32
#define THREADS 256

// float offsets in dynamic smem
#define SW_OFF 0            // 2 x 4608 weight frag buffers
#define HA_OFF 9216         // hidden 128 x 132 (sA buffers alias its head)
#define SMEM_FLOATS (9216 + 16896)
#define SMEM_BYTES (SMEM_FLOATS * 4)   // 104448

__device__ float g_acc[50000 * HDIM];

__device__ __forceinline__ float to_tf32(float x) {
    unsigned u;
    asm("cvt.rna.tf32.f32 %0, %1;" : "=r"(u) : "f"(x));
    return __uint_as_float(u);
}

__device__ __forceinline__ void mma8(float c[4], const unsigned a[4], unsigned b0, unsigned b1) {
    asm volatile(
        "mma.sync.aligned.m16n8k8.row.col.f32.tf32.tf32.f32 "
        "{%0,%1,%2,%3}, {%4,%5,%6,%7}, {%8,%9}, {%0,%1,%2,%3};"
        : "+f"(c[0]), "+f"(c[1]), "+f"(c[2]), "+f"(c[3])
        : "r"(a[0]), "r"(a[1]), "r"(a[2]), "r"(a[3]), "r"(b0), "r"(b1));
}

__device__ __forceinline__ void red2(float* p, float a, float b) {
    asm volatile("red.global.add.v2.f32 [%0], {%1, %2};" :: "l"(p), "f"(a), "f"(b) : "memory");
}

// ---- mma over one staged 32-k chunk ----
// A from smem rows (stride ASTRIDE, warp-private rows), W from fragment buffer:
// addr(kb, lane, j2) = kb*1152 + lane*36 + j2*4  (float4 = {b0(j=2j2), b1(2j2), b0(2j2+1), b1(2j2+1)})
template <int ASTRIDE>
__device__ __forceinline__ void mma_chunk(float c[16][4], const float* As, const float* Ws,
                                          int lane, int g, int tig, int rbase) {
#pragma unroll
    for (int kb = 0; kb < 4; kb++) {
        unsigned a[4];
        const float* ap = As + (rbase + g) * ASTRIDE + kb * 8 + tig;
        a[0] = __float_as_uint(ap[0]);
        a[1] = __float_as_uint(ap[8 * ASTRIDE]);
        a[2] = __float_as_uint(ap[4]);
        a[3] = __float_as_uint(ap[8 * ASTRIDE + 4]);
        const float4* wp = (const float4*)(Ws + kb * 1152 + lane * 36);
#pragma unroll
        for (int half = 0; half < 2; half++) {
            float4 w[4];
#pragma unroll
            for (int q = 0; q < 4; q++) w[q] = wp[half * 4 + q];
#pragma unroll
            for (int q = 0; q < 4; q++) {
                int j = half * 8 + q * 2;
                mma8(c[j],     a, __float_as_uint(w[q].x), __float_as_uint(w[q].y));
                mma8(c[j + 1], a, __float_as_uint(w[q].z), __float_as_uint(w[q].w));
            }
        }
    }
}

// ---- weight staging: global [K,128] row-major -> fragment layout ----
__device__ __forceinline__ void stage_W(float* sWd, const float* W, int kt, int tid) {
    float4 wv[4];
#pragma unroll
    for (int i = 0; i < 4; i++) {
        int idx4 = tid + i * 256;
        int kk = idx4 >> 5;
        int n0 = (idx4 & 31) * 4;
        wv[i] = *(const float4*)(W + (size_t)(kt + kk) * HDIM + n0);
    }
#pragma unroll
    for (int i = 0; i < 4; i++) {
        int idx4 = tid + i * 256;
        int kk = idx4 >> 5;
        int n0 = (idx4 & 31) * 4;
        float v[4] = {wv[i].x, wv[i].y, wv[i].z, wv[i].w};
#pragma unroll
        for (int u = 0; u < 4; u++) {
            int n = n0 + u;
            int j = n >> 3;
            sWd[(kk >> 3) * 1152 + ((n & 7) * 4 + (kk & 3)) * 36
                + (j >> 1) * 4 + (j & 1) * 2 + ((kk >> 2) & 1)] = to_tf32(v[u]);
        }
    }
}

// ---- A staging (ldg half: into regs; sts half: into smem stride-36) ----
__device__ __forceinline__ void ldg_Ae(float4 av[4], const int* __restrict__ senders,
                                       const int* __restrict__ receivers,
                                       const float* __restrict__ nodef,
                                       const float* __restrict__ edgef,
                                       int e0, int E, int kt, int tid) {
#pragma unroll
    for (int i = 0; i < 4; i++) {
        int idx4 = tid + i * 256;
        int r = idx4 >> 3;
        int kk0 = (idx4 & 7) * 4;
        int e = min(e0 + r, E - 1);
        int kg = kt + kk0;
        const float* src;
        if (kg < HDIM)           src = nodef + (size_t)senders[e] * HDIM + kg;
        else if (kg < 2 * HDIM)  src = nodef + (size_t)receivers[e] * HDIM + (kg - HDIM);
        else                     src = edgef + (size_t)e * HDIM + (kg - 2 * HDIM);
        av[i] = *(const float4*)src;
    }
}

__device__ __forceinline__ void ldg_An(float4 av[4], const float* __restrict__ nodef,
                                       float* acc, int n0base, int N, int nvalid,
                                       int kt, int tid) {
#pragma unroll
    for (int i = 0; i < 4; i++) {
        int idx4 = tid + i * 256;
        int r = idx4 >> 3;
        int kk0 = (idx4 & 7) * 4;
        int nd = min(n0base + r, N - 1);
        int kg = kt + kk0;
        if (kg < HDIM) {
            av[i] = *(const float4*)(nodef + (size_t)nd * HDIM + kg);
        } else {
            float4* p = (float4*)(acc + (size_t)nd * HDIM + (kg - HDIM));
            av[i] = *p;
            if (r < nvalid) *p = make_float4(0.f, 0.f, 0.f, 0.f);  // zero-after-read
        }
    }
}

__device__ __forceinline__ void sts_A(const float4 av[4], float* sAd, int tid) {
#pragma unroll
    for (int i = 0; i < 4; i++) {
        int idx4 = tid + i * 256;
        int r = idx4 >> 3;
        int kk0 = (idx4 & 7) * 4;
        float4 o = make_float4(to_tf32(av[i].x), to_tf32(av[i].y),
                               to_tf32(av[i].z), to_tf32(av[i].w));
        *(float4*)(sAd + r * 36 + kk0) = o;
    }
}

__device__ __forceinline__ void zero_c(float c[16][4]) {
#pragma unroll
    for (int j = 0; j < 16; j++)
#pragma unroll
        for (int i = 0; i < 4; i++) c[j][i] = 0.f;
}

__device__ __forceinline__ void bias_relu_store(float c[16][4], const float* bias, float* hdst,
                                                int g, int tig, int rbase) {
#pragma unroll
    for (int j = 0; j < 16; j++) {
        int n0 = 8 * j + 2 * tig;
        float b0 = bias[n0], b1 = bias[n0 + 1];
        hdst[(rbase + g) * 132 + n0]         = to_tf32(fmaxf(c[j][0] + b0, 0.f));
        hdst[(rbase + g) * 132 + n0 + 1]     = to_tf32(fmaxf(c[j][1] + b1, 0.f));
        hdst[(rbase + g + 8) * 132 + n0]     = to_tf32(fmaxf(c[j][2] + b0, 0.f));
        hdst[(rbase + g + 8) * 132 + n0 + 1] = to_tf32(fmaxf(c[j][3] + b1, 0.f));
    }
}

__device__ __forceinline__ void ln_stats(float c[16][4], const float* bias,
                                         float& mu0, float& rs0, float& mu1, float& rs1,
                                         int tig) {
    float s0 = 0.f, q0 = 0.f, s1 = 0.f, q1 = 0.f;
#pragma unroll
    for (int j = 0; j < 16; j++) {
        int n0 = 8 * j + 2 * tig;
        float b0 = bias[n0], b1 = bias[n0 + 1];
        c[j][0] += b0; c[j][1] += b1; c[j][2] += b0; c[j][3] += b1;
        s0 += c[j][0] + c[j][1];
        q0 += c[j][0] * c[j][0] + c[j][1] * c[j][1];
        s1 += c[j][2] + c[j][3];
        q1 += c[j][2] * c[j][2] + c[j][3] * c[j][3];
    }
#pragma unroll
    for (int m = 1; m < 4; m <<= 1) {
        s0 += __shfl_xor_sync(0xffffffffu, s0, m);
        q0 += __shfl_xor_sync(0xffffffffu, q0, m);
        s1 += __shfl_xor_sync(0xffffffffu, s1, m);
        q1 += __shfl_xor_sync(0xffffffffu, q1, m);
    }
    mu0 = s0 * (1.f / HDIM);
    mu1 = s1 * (1.f / HDIM);
    float v0 = q0 * (1.f / HDIM) - mu0 * mu0;
    float v1 = q1 * (1.f / HDIM) - mu1 * mu1;
    rs0 = rsqrtf(v0 + 1e-5f);
    rs1 = rsqrtf(v1 + 1e-5f);
}

// ============================ EDGE KERNEL ============================
__global__ void __launch_bounds__(THREADS, 2)
edge_kernel(const int* __restrict__ senders, const int* __restrict__ receivers,
            const float* __restrict__ nodef, const float* __restrict__ edgef,
            const float* __restrict__ eW0, const float* __restrict__ eb0,
            const float* __restrict__ eW1, const float* __restrict__ eb1,
            const float* __restrict__ eW2, const float* __restrict__ eb2,
            const float* __restrict__ egm, const float* __restrict__ ebeta,
            float* __restrict__ out_edge, float* __restrict__ acc, int E) {
    extern __shared__ float sm[];
    float* sW = sm + SW_OFF;       // 2 x 4608
    float* hA = sm + HA_OFF;       // 128 x 132 ; sA buffers alias its head
    float* sA = hA;                // 2 x 4608

    int tid = threadIdx.x, warp = tid >> 5, lane = tid & 31;
    int g = lane >> 2, tig = lane & 3, rbase = warp * 16;
    int e0 = blockIdx.x * TE;
    int nvalid = min(TE, E - e0);

    float c[16][4];
    zero_c(c);

    // ---- stage 0: K = 384, pipelined A-gather + W staging ----
    {
        float4 av[4];
        ldg_Ae(av, senders, receivers, nodef, edgef, e0, E, 0, tid);
        sts_A(av, sA, tid);
        stage_W(sW, eW0, 0, tid);
        __syncthreads();
#pragma unroll 1
        for (int t = 0; t < 12; t++) {
            if (t < 11)
                ldg_Ae(av, senders, receivers, nodef, edgef, e0, E, (t + 1) * KC, tid);
            mma_chunk<36>(c, sA + (t & 1) * 4608, sW + (t & 1) * 4608, lane, g, tig, rbase);
            if (t < 11) {
                sts_A(av, sA + ((t + 1) & 1) * 4608, tid);
                stage_W(sW + ((t + 1) & 1) * 4608, eW0, (t + 1) * KC, tid);
            }
            __syncthreads();
        }
    }
    bias_relu_store(c, eb0, hA, g, tig, rbase);   // hA rows warp-private

    // ---- stage 1: K = 128 (A in place in hA) ----
    zero_c(c);
    stage_W(sW, eW1, 0, tid);
    __syncthreads();
#pragma unroll 1
    for (int t = 0; t < 4; t++) {
        mma_chunk<132>(c, hA + t * KC, sW + (t & 1) * 4608, lane, g, tig, rbase);
        if (t < 3) stage_W(sW + ((t + 1) & 1) * 4608, eW1, (t + 1) * KC, tid);
        __syncthreads();
    }
    bias_relu_store(c, eb1, hA, g, tig, rbase);   // in-place, warp-private

    // ---- stage 2: K = 128, no relu ----
    zero_c(c);
    stage_W(sW, eW2, 0, tid);
    __syncthreads();
#pragma unroll 1
    for (int t = 0; t < 4; t++) {
        mma_chunk<132>(c, hA + t * KC, sW + (t & 1) * 4608, lane, g, tig, rbase);
        if (t < 3) stage_W(sW + ((t + 1) & 1) * 4608, eW2, (t + 1) * KC, tid);
        __syncthreads();
    }

    // ---- LayerNorm + residual + scatter-add ----
    float mu0, rs0, mu1, rs1;
    ln_stats(c, eb2, mu0, rs0, mu1, rs1, tig);

    int r0 = rbase + g, r1 = rbase + g + 8;
    bool ok0 = r0 < nvalid, ok1 = r1 < nvalid;
    size_t e_0 = (size_t)(e0 + r0), e_1 = (size_t)(e0 + r1);
    int rc0 = ok0 ? receivers[e_0] : 0;
    int rc1 = ok1 ? receivers[e_1] : 0;

#pragma unroll
    for (int j = 0; j < 16; j++) {
        int n0 = 8 * j + 2 * tig;
        float g0 = egm[n0], g1 = egm[n0 + 1];
        float be0 = ebeta[n0], be1 = ebeta[n0 + 1];
        if (ok0) {
            float y0 = (c[j][0] - mu0) * rs0 * g0 + be0;
            float y1 = (c[j][1] - mu0) * rs0 * g1 + be1;
            float2 ef = *(const float2*)(edgef + e_0 * HDIM + n0);
            __stcs((float2*)(out_edge + e_0 * HDIM + n0), make_float2(y0 + ef.x, y1 + ef.y));
            red2(&acc[(size_t)rc0 * HDIM + n0], y0, y1);
        }
        if (ok1) {
            float y0 = (c[j][2] - mu1) * rs1 * g0 + be0;
            float y1 = (c[j][3] - mu1) * rs1 * g1 + be1;
            float2 ef = *(const float2*)(edgef + e_1 * HDIM + n0);
            __stcs((float2*)(out_edge + e_1 * HDIM + n0), make_float2(y0 + ef.x, y1 + ef.y));
            red2(&acc[(size_t)rc1 * HDIM + n0], y0, y1);
        }
    }
}

// ============================ NODE KERNEL ============================
__global__ void __launch_bounds__(THREADS, 2)
node_kernel(const float* __restrict__ nodef, float* __restrict__ acc,
            const float* __restrict__ nW0, const float* __restrict__ nb0,
            const float* __restrict__ nW1, const float* __restrict__ nb1,
            const float* __restrict__ nW2, const float* __restrict__ nb2,
            const float* __restrict__ ngm, const float* __restrict__ nbeta,
            float* __restrict__ out_node, int N) {
    extern __shared__ float sm[];
    float* sW = sm + SW_OFF;
    float* hA = sm + HA_OFF;
    float* sA = hA;

    int tid = threadIdx.x, warp = tid >> 5, lane = tid & 31;
    int g = lane >> 2, tig = lane & 3, rbase = warp * 16;
    int n0base = blockIdx.x * TE;
    int nvalid = min(TE, N - n0base);

    float c[16][4];
    zero_c(c);

    // ---- stage 0: K = 256 ([nf | acc], acc zeroed after read) ----
    {
        float4 av[4];
        ldg_An(av, nodef, acc, n0base, N, nvalid, 0, tid);
        sts_A(av, sA, tid);
        stage_W(sW, nW0, 0, tid);
        __syncthreads();
#pragma unroll 1
        for (int t = 0; t < 8; t++) {
            if (t < 7)
                ldg_An(av, nodef, acc, n0base, N, nvalid, (t + 1) * KC, tid);
            mma_chunk<36>(c, sA + (t & 1) * 4608, sW + (t & 1) * 4608, lane, g, tig, rbase);
            if (t < 7) {
                sts_A(av, sA + ((t + 1) & 1) * 4608, tid);
                stage_W(sW + ((t + 1) & 1) * 4608, nW0, (t + 1) * KC, tid);
            }
            __syncthreads();
        }
    }
    bias_relu_store(c, nb0, hA, g, tig, rbase);

    // ---- stage 1 ----
    zero_c(c);
    stage_W(sW, nW1, 0, tid);
    __syncthreads();
#pragma unroll 1
    for (int t = 0; t < 4; t++) {
        mma_chunk<132>(c, hA + t * KC, sW + (t & 1) * 4608, lane, g, tig, rbase);
        if (t < 3) stage_W(sW + ((t + 1) & 1) * 4608, nW1, (t + 1) * KC, tid);
        __syncthreads();
    }
    bias_relu_store(c, nb1, hA, g, tig, rbase);

    // ---- stage 2 ----
    zero_c(c);
    stage_W(sW, nW2, 0, tid);
    __syncthreads();
#pragma unroll 1
    for (int t = 0; t < 4; t++) {
        mma_chunk<132>(c, hA + t * KC, sW + (t & 1) * 4608, lane, g, tig, rbase);
        if (t < 3) stage_W(sW + ((t + 1) & 1) * 4608, nW2, (t + 1) * KC, tid);
        __syncthreads();
    }

    // ---- LayerNorm + residual ----
    float mu0, rs0, mu1, rs1;
    ln_stats(c, nb2, mu0, rs0, mu1, rs1, tig);

    int r0 = rbase + g, r1 = rbase + g + 8;
    bool ok0 = r0 < nvalid, ok1 = r1 < nvalid;
    size_t nd0 = (size_t)(n0base + r0), nd1 = (size_t)(n0base + r1);

#pragma unroll
    for (int j = 0; j < 16; j++) {
        int n0 = 8 * j + 2 * tig;
        float g0 = ngm[n0], g1 = ngm[n0 + 1];
        float be0 = nbeta[n0], be1 = nbeta[n0 + 1];
        if (ok0) {
            float y0 = (c[j][0] - mu0) * rs0 * g0 + be0;
            float y1 = (c[j][1] - mu0) * rs0 * g1 + be1;
            float2 nf = *(const float2*)(nodef + nd0 * HDIM + n0);
            __stcs((float2*)(out_node + nd0 * HDIM + n0), make_float2(y0 + nf.x, y1 + nf.y));
        }
        if (ok1) {
            float y0 = (c[j][2] - mu1) * rs1 * g0 + be0;
            float y1 = (c[j][3] - mu1) * rs1 * g1 + be1;
            float2 nf = *(const float2*)(nodef + nd1 * HDIM + n0);
            __stcs((float2*)(out_node + nd1 * HDIM + n0), make_float2(y0 + nf.x, y1 + nf.y));
        }
    }
}

// ============================ LAUNCH ============================
extern "C" void kernel_launch(void* const* d_in, const int* in_sizes, int n_in,
                              void* d_out, int out_size) {
    const int*   senders   = (const int*)d_in[0];
    const int*   receivers = (const int*)d_in[1];
    const float* nodef     = (const float*)d_in[2];
    const float* edgef     = (const float*)d_in[3];
    const float* eW0 = (const float*)d_in[4];
    const float* eb0 = (const float*)d_in[5];
    const float* eW1 = (const float*)d_in[6];
    const float* eb1 = (const float*)d_in[7];
    const float* eW2 = (const float*)d_in[8];
    const float* eb2 = (const float*)d_in[9];
    const float* eg  = (const float*)d_in[10];
    const float* ebeta = (const float*)d_in[11];
    const float* nW0 = (const float*)d_in[12];
    const float* nb0 = (const float*)d_in[13];
    const float* nW1 = (const float*)d_in[14];
    const float* nb1 = (const float*)d_in[15];
    const float* nW2 = (const float*)d_in[16];
    const float* nb2 = (const float*)d_in[17];
    const float* ng  = (const float*)d_in[18];
    const float* nbeta = (const float*)d_in[19];

    int E = in_sizes[1];
    int N = in_sizes[2] / HDIM;

    float* out_node = (float*)d_out;
    float* out_edge = out_node + (size_t)N * HDIM;

    float* acc = nullptr;
    cudaGetSymbolAddress((void**)&acc, g_acc);

    cudaFuncSetAttribute(edge_kernel, cudaFuncAttributeMaxDynamicSharedMemorySize, SMEM_BYTES);
    cudaFuncSetAttribute(node_kernel, cudaFuncAttributeMaxDynamicSharedMemorySize, SMEM_BYTES);

    edge_kernel<<<(E + TE - 1) / TE, THREADS, SMEM_BYTES>>>(
        senders, receivers, nodef, edgef,
        eW0, eb0, eW1, eb1, eW2, eb2, eg, ebeta,
        out_edge, acc, E);
    node_kernel<<<(N + TE - 1) / TE, THREADS, SMEM_BYTES>>>(
        nodef, acc, nW0, nb0, nW1, nb1, nW2, nb2, ng, nbeta,
        out_node, N);
}

// round 4
// speedup vs baseline: 4.6206x; 1.1569x over previous
#include <cuda_runtime.h>
#include <cstdint>

// GraphNetBlock — mma.sync tf32, v3:
//  * node-projection trick: P = nodef @ [eW0_s | eW0_r | nW0_top] computed once
//    per node (50k rows) instead of per edge (600k) -> 105 -> 45 GFLOP
//  * all MLP stages uniform K=128; A staged once per tile (contiguous)
//  * W register-prefetch one chunk ahead (LDG latency hidden under mma)
//  * 2 CTAs/SM, warp-private in-place hidden buffer, red.v2 scatter

#define H 128
#define TE 128
#define KC 32
#define THREADS 256

// float offsets in dynamic smem
#define SW_OFF 0                 // 2 x 4608 weight frag buffers
#define HA_OFF 9216              // A / hidden: 128 x 132
#define BIAS_F 26112             // 5 x 128
#define SSR_F  26752             // sS[128], sR[128] ints
#define SMEM_FLOATS 27008
#define SMEM_BYTES (SMEM_FLOATS * 4)   // 108032

__device__ float g_acc[50000 * H];
__device__ float g_proj[50000 * 384];

__device__ __forceinline__ float to_tf32(float x) {
    unsigned u;
    asm("cvt.rna.tf32.f32 %0, %1;" : "=r"(u) : "f"(x));
    return __uint_as_float(u);
}

__device__ __forceinline__ void mma8(float c[4], const unsigned a[4], unsigned b0, unsigned b1) {
    asm volatile(
        "mma.sync.aligned.m16n8k8.row.col.f32.tf32.tf32.f32 "
        "{%0,%1,%2,%3}, {%4,%5,%6,%7}, {%8,%9}, {%0,%1,%2,%3};"
        : "+f"(c[0]), "+f"(c[1]), "+f"(c[2]), "+f"(c[3])
        : "r"(a[0]), "r"(a[1]), "r"(a[2]), "r"(a[3]), "r"(b0), "r"(b1));
}

__device__ __forceinline__ void red2(float* p, float a, float b) {
    asm volatile("red.global.add.v2.f32 [%0], {%1, %2};" :: "l"(p), "f"(a), "f"(b) : "memory");
}

// ---- mma over one staged 32-k chunk; A stride 132; W fragment layout ----
__device__ __forceinline__ void mma_chunk(float c[16][4], const float* As, const float* Ws,
                                          int lane, int g, int tig, int rbase) {
#pragma unroll
    for (int kb = 0; kb < 4; kb++) {
        unsigned a[4];
        const float* ap = As + (rbase + g) * 132 + kb * 8 + tig;
        a[0] = __float_as_uint(ap[0]);
        a[1] = __float_as_uint(ap[8 * 132]);
        a[2] = __float_as_uint(ap[4]);
        a[3] = __float_as_uint(ap[8 * 132 + 4]);
        const float4* wp = (const float4*)(Ws + kb * 1152 + lane * 36);
#pragma unroll
        for (int half = 0; half < 2; half++) {
            float4 w[4];
#pragma unroll
            for (int q = 0; q < 4; q++) w[q] = wp[half * 4 + q];
#pragma unroll
            for (int q = 0; q < 4; q++) {
                int j = half * 8 + q * 2;
                mma8(c[j],     a, __float_as_uint(w[q].x), __float_as_uint(w[q].y));
                mma8(c[j + 1], a, __float_as_uint(w[q].z), __float_as_uint(w[q].w));
            }
        }
    }
}

// ---- weight staging split: LDG half / STS half (fragment layout) ----
__device__ __forceinline__ void ldg_W(float4 wv[4], const float* __restrict__ W, int kt, int tid) {
#pragma unroll
    for (int i = 0; i < 4; i++) {
        int idx4 = tid + (i << 8);
        int kk = idx4 >> 5;
        int n0 = (idx4 & 31) << 2;
        wv[i] = *(const float4*)(W + (size_t)(kt + kk) * H + n0);
    }
}
__device__ __forceinline__ void sts_W(const float4 wv[4], float* sWd, int tid) {
#pragma unroll
    for (int i = 0; i < 4; i++) {
        int idx4 = tid + (i << 8);
        int kk = idx4 >> 5;
        int n0 = (idx4 & 31) << 2;
        float v[4] = {wv[i].x, wv[i].y, wv[i].z, wv[i].w};
#pragma unroll
        for (int u = 0; u < 4; u++) {
            int n = n0 + u;
            int j = n >> 3;
            sWd[(kk >> 3) * 1152 + ((n & 7) * 4 + (kk & 3)) * 36
                + (j >> 1) * 4 + (j & 1) * 2 + ((kk >> 2) & 1)] = to_tf32(v[u]);
        }
    }
}

__device__ __forceinline__ void zero_c(float c[16][4]) {
#pragma unroll
    for (int j = 0; j < 16; j++)
#pragma unroll
        for (int i = 0; i < 4; i++) c[j][i] = 0.f;
}

// ================= unified kernel: MODE 0=proj, 1=edge, 2=node =================
template <int MODE>
__global__ void __launch_bounds__(THREADS, 2)
gnb_kernel(const int* __restrict__ send, const int* __restrict__ recv,
           const float* __restrict__ nodef, const float* __restrict__ resid,
           float* __restrict__ acc, float* __restrict__ proj,
           const float* __restrict__ Wa, const float* __restrict__ Wb,
           const float* __restrict__ Wc,
           const float* __restrict__ pb0, const float* __restrict__ pb1,
           const float* __restrict__ pb2,
           const float* __restrict__ gam, const float* __restrict__ bet,
           float* __restrict__ out, int rows) {
    extern __shared__ float sm[];
    float* sW = sm + SW_OFF;
    float* hA = sm + HA_OFF;
    int* sS = (int*)(sm + SSR_F);
    int* sR = (int*)(sm + SSR_F + 128);

    const int tid = threadIdx.x, lane = tid & 31, warp = tid >> 5;
    const int g = lane >> 2, tig = lane & 3, rbase = warp * 16;
    const int base = blockIdx.x * TE;
    const int nvalid = min(TE, rows - base);

    // ---- init: biases + edge indices ----
    if (MODE != 0 && tid < H) {
        sm[BIAS_F + 0 * H + tid] = pb0[tid];
        sm[BIAS_F + 1 * H + tid] = pb1[tid];
        sm[BIAS_F + 2 * H + tid] = pb2[tid];
        sm[BIAS_F + 3 * H + tid] = gam[tid];
        sm[BIAS_F + 4 * H + tid] = bet[tid];
    }
    if (MODE == 1) {
        if (tid < TE) {
            int e = min(base + tid, rows - 1);
            sS[tid] = send[e];
            sR[tid] = recv[e];
        }
    }

    // ---- stage A tile into hA (128 x 128, tf32, stride 132) ----
#pragma unroll
    for (int i = 0; i < 16; i++) {
        int idx4 = tid + (i << 8);
        int r = idx4 >> 5;
        int c4 = (idx4 & 31) << 2;
        int rg = min(base + r, rows - 1);
        float4 v;
        if (MODE == 0) {
            v = *(const float4*)(nodef + (size_t)rg * H + c4);
        } else if (MODE == 1) {
            v = *(const float4*)(resid + (size_t)rg * H + c4);
        } else {
            float4* zp = (float4*)(acc + (size_t)rg * H + c4);
            v = *zp;
            if (base + r < rows) *zp = make_float4(0.f, 0.f, 0.f, 0.f);  // restore zeros
        }
        *(float4*)(hA + r * 132 + c4) =
            make_float4(to_tf32(v.x), to_tf32(v.y), to_tf32(v.z), to_tf32(v.w));
    }

    float c[16][4];
    const int r0 = rbase + g, r1 = rbase + g + 8;

#pragma unroll 1
    for (int s = 0; s < 3; s++) {
        const float* W = (s == 0) ? Wa : (s == 1) ? Wb : Wc;
        zero_c(c);
        float4 wv[4];
        ldg_W(wv, W, 0, tid);
        sts_W(wv, sW, tid);
        __syncthreads();   // also guards hA writes (staging / previous epilogue)
#pragma unroll 1
        for (int t = 0; t < 4; t++) {
            if (t < 3) ldg_W(wv, W, (t + 1) * KC, tid);
            mma_chunk(c, hA + t * KC, sW + (t & 1) * 4608, lane, g, tig, rbase);
            if (t < 3) sts_W(wv, sW + ((t + 1) & 1) * 4608, tid);
            __syncthreads();
        }

        // ================= epilogues =================
        if (MODE == 0) {
            // raw store to proj col-block s
            bool ok0 = r0 < nvalid, ok1 = r1 < nvalid;
            float* p0 = proj + (size_t)(base + r0) * 384 + s * 128;
            float* p1 = proj + (size_t)(base + r1) * 384 + s * 128;
#pragma unroll
            for (int j = 0; j < 16; j++) {
                int n0 = 8 * j + 2 * tig;
                if (ok0) *(float2*)(p0 + n0) = make_float2(c[j][0], c[j][1]);
                if (ok1) *(float2*)(p1 + n0) = make_float2(c[j][2], c[j][3]);
            }
        } else if (s == 0) {
            const float* bS = sm + BIAS_F;
            if (MODE == 1) {
                const float* sp0 = proj + (size_t)sS[r0] * 384;
                const float* rp0 = proj + (size_t)sR[r0] * 384 + 128;
                const float* sp1 = proj + (size_t)sS[r1] * 384;
                const float* rp1 = proj + (size_t)sR[r1] * 384 + 128;
#pragma unroll
                for (int j = 0; j < 16; j++) {
                    int n0 = 8 * j + 2 * tig;
                    float2 a0 = *(const float2*)(sp0 + n0);
                    float2 b0 = *(const float2*)(rp0 + n0);
                    float2 a1 = *(const float2*)(sp1 + n0);
                    float2 b1 = *(const float2*)(rp1 + n0);
                    float bb0 = bS[n0], bb1 = bS[n0 + 1];
                    hA[r0 * 132 + n0]     = to_tf32(fmaxf(c[j][0] + a0.x + b0.x + bb0, 0.f));
                    hA[r0 * 132 + n0 + 1] = to_tf32(fmaxf(c[j][1] + a0.y + b0.y + bb1, 0.f));
                    hA[r1 * 132 + n0]     = to_tf32(fmaxf(c[j][2] + a1.x + b1.x + bb0, 0.f));
                    hA[r1 * 132 + n0 + 1] = to_tf32(fmaxf(c[j][3] + a1.y + b1.y + bb1, 0.f));
                }
            } else {
                const float* p0 = proj + (size_t)min(base + r0, rows - 1) * 384 + 256;
                const float* p1 = proj + (size_t)min(base + r1, rows - 1) * 384 + 256;
#pragma unroll
                for (int j = 0; j < 16; j++) {
                    int n0 = 8 * j + 2 * tig;
                    float2 a0 = *(const float2*)(p0 + n0);
                    float2 a1 = *(const float2*)(p1 + n0);
                    float bb0 = bS[n0], bb1 = bS[n0 + 1];
                    hA[r0 * 132 + n0]     = to_tf32(fmaxf(c[j][0] + a0.x + bb0, 0.f));
                    hA[r0 * 132 + n0 + 1] = to_tf32(fmaxf(c[j][1] + a0.y + bb1, 0.f));
                    hA[r1 * 132 + n0]     = to_tf32(fmaxf(c[j][2] + a1.x + bb0, 0.f));
                    hA[r1 * 132 + n0 + 1] = to_tf32(fmaxf(c[j][3] + a1.y + bb1, 0.f));
                }
            }
        } else if (s == 1) {
            const float* bS = sm + BIAS_F + H;
#pragma unroll
            for (int j = 0; j < 16; j++) {
                int n0 = 8 * j + 2 * tig;
                float bb0 = bS[n0], bb1 = bS[n0 + 1];
                hA[r0 * 132 + n0]     = to_tf32(fmaxf(c[j][0] + bb0, 0.f));
                hA[r0 * 132 + n0 + 1] = to_tf32(fmaxf(c[j][1] + bb1, 0.f));
                hA[r1 * 132 + n0]     = to_tf32(fmaxf(c[j][2] + bb0, 0.f));
                hA[r1 * 132 + n0 + 1] = to_tf32(fmaxf(c[j][3] + bb1, 0.f));
            }
        } else {
            // final: bias + LayerNorm + residual (+ scatter for edge)
            const float* bS = sm + BIAS_F + 2 * H;
            float s0 = 0.f, q0 = 0.f, s1 = 0.f, q1 = 0.f;
#pragma unroll
            for (int j = 0; j < 16; j++) {
                int n0 = 8 * j + 2 * tig;
                float bb0 = bS[n0], bb1 = bS[n0 + 1];
                c[j][0] += bb0; c[j][1] += bb1; c[j][2] += bb0; c[j][3] += bb1;
                s0 += c[j][0] + c[j][1];
                q0 += c[j][0] * c[j][0] + c[j][1] * c[j][1];
                s1 += c[j][2] + c[j][3];
                q1 += c[j][2] * c[j][2] + c[j][3] * c[j][3];
            }
#pragma unroll
            for (int m = 1; m < 4; m <<= 1) {
                s0 += __shfl_xor_sync(0xffffffffu, s0, m);
                q0 += __shfl_xor_sync(0xffffffffu, q0, m);
                s1 += __shfl_xor_sync(0xffffffffu, s1, m);
                q1 += __shfl_xor_sync(0xffffffffu, q1, m);
            }
            float mu0 = s0 * (1.f / H), mu1 = s1 * (1.f / H);
            float rs0 = rsqrtf(q0 * (1.f / H) - mu0 * mu0 + 1e-5f);
            float rs1 = rsqrtf(q1 * (1.f / H) - mu1 * mu1 + 1e-5f);

            bool ok0 = r0 < nvalid, ok1 = r1 < nvalid;
            size_t ro0 = (size_t)(base + r0) * H, ro1 = (size_t)(base + r1) * H;
            int rc0 = (MODE == 1 && ok0) ? sR[r0] : 0;
            int rc1 = (MODE == 1 && ok1) ? sR[r1] : 0;
            const float* gS = sm + BIAS_F + 3 * H;
            const float* eS = sm + BIAS_F + 4 * H;
#pragma unroll
            for (int j = 0; j < 16; j++) {
                int n0 = 8 * j + 2 * tig;
                float g0 = gS[n0], g1 = gS[n0 + 1];
                float be0 = eS[n0], be1 = eS[n0 + 1];
                if (ok0) {
                    float y0 = (c[j][0] - mu0) * rs0 * g0 + be0;
                    float y1 = (c[j][1] - mu0) * rs0 * g1 + be1;
                    float2 rf = *(const float2*)(resid + ro0 + n0);
                    __stcs((float2*)(out + ro0 + n0), make_float2(y0 + rf.x, y1 + rf.y));
                    if (MODE == 1) red2(&acc[(size_t)rc0 * H + n0], y0, y1);
                }
                if (ok1) {
                    float y0 = (c[j][2] - mu1) * rs1 * g0 + be0;
                    float y1 = (c[j][3] - mu1) * rs1 * g1 + be1;
                    float2 rf = *(const float2*)(resid + ro1 + n0);
                    __stcs((float2*)(out + ro1 + n0), make_float2(y0 + rf.x, y1 + rf.y));
                    if (MODE == 1) red2(&acc[(size_t)rc1 * H + n0], y0, y1);
                }
            }
        }
    }
}

// ============================ LAUNCH ============================
extern "C" void kernel_launch(void* const* d_in, const int* in_sizes, int n_in,
                              void* d_out, int out_size) {
    const int*   senders   = (const int*)d_in[0];
    const int*   receivers = (const int*)d_in[1];
    const float* nodef     = (const float*)d_in[2];
    const float* edgef     = (const float*)d_in[3];
    const float* eW0 = (const float*)d_in[4];
    const float* eb0 = (const float*)d_in[5];
    const float* eW1 = (const float*)d_in[6];
    const float* eb1 = (const float*)d_in[7];
    const float* eW2 = (const float*)d_in[8];
    const float* eb2 = (const float*)d_in[9];
    const float* eg  = (const float*)d_in[10];
    const float* ebeta = (const float*)d_in[11];
    const float* nW0 = (const float*)d_in[12];
    const float* nb0 = (const float*)d_in[13];
    const float* nW1 = (const float*)d_in[14];
    const float* nb1 = (const float*)d_in[15];
    const float* nW2 = (const float*)d_in[16];
    const float* nb2 = (const float*)d_in[17];
    const float* ng  = (const float*)d_in[18];
    const float* nbeta = (const float*)d_in[19];

    int E = in_sizes[1];
    int N = in_sizes[2] / H;

    float* out_node = (float*)d_out;
    float* out_edge = out_node + (size_t)N * H;

    float *acc = nullptr, *proj = nullptr;
    cudaGetSymbolAddress((void**)&acc, g_acc);
    cudaGetSymbolAddress((void**)&proj, g_proj);

    cudaFuncSetAttribute(gnb_kernel<0>, cudaFuncAttributeMaxDynamicSharedMemorySize, SMEM_BYTES);
    cudaFuncSetAttribute(gnb_kernel<1>, cudaFuncAttributeMaxDynamicSharedMemorySize, SMEM_BYTES);
    cudaFuncSetAttribute(gnb_kernel<2>, cudaFuncAttributeMaxDynamicSharedMemorySize, SMEM_BYTES);

    int ngrid = (N + TE - 1) / TE;
    int egrid = (E + TE - 1) / TE;

    // proj: P = nodef @ [eW0_send | eW0_recv | nW0_top]
    gnb_kernel<0><<<ngrid, THREADS, SMEM_BYTES>>>(
        nullptr, nullptr, nodef, nullptr, acc, proj,
        eW0, eW0 + (size_t)128 * H, nW0,
        eb0, eb0, eb0, eg, ebeta, nullptr, N);

    // edge MLP: ef @ eW0_bot (+gathered P) -> eW1 -> eW2 -> LN -> scatter
    gnb_kernel<1><<<egrid, THREADS, SMEM_BYTES>>>(
        senders, receivers, nodef, edgef, acc, proj,
        eW0 + (size_t)256 * H, eW1, eW2,
        eb0, eb1, eb2, eg, ebeta, out_edge, E);

    // node MLP: acc @ nW0_bot (+P nf-block) -> nW1 -> nW2 -> LN
    gnb_kernel<2><<<ngrid, THREADS, SMEM_BYTES>>>(
        nullptr, nullptr, nodef, nodef, acc, proj,
        nW0 + (size_t)128 * H, nW1, nW2,
        nb0, nb1, nb2, ng, nbeta, out_node, N);
}